// round 1
// baseline (speedup 1.0000x reference)
#include <cuda_runtime.h>
#include <stdint.h>

#define IN_DIM   4096
#define OUT_DIM  1024
#define CAP      96      // max nonzeros kept per output row (mean ~40, sigma ~6.3; 96 = ~9 sigma)
#define R        32      // x rows per block
#define KT       1024    // K columns per phase
#define NPH      4       // IN_DIM / KT
#define TPB      1024
#define XS_STRIDE 1025   // floats; 1025 % 32 == 1  -> bank = (row + col) % 32, conflict-free
#define SMEM_BYTES (R * XS_STRIDE * 4)   // 131200

// Compacted sparse table for Phi (rebuilt every launch; deterministic).
// g_tab[o*CAP + j] = { byte offset of col within its KT-quarter, fp32 value bits }
// g_bnd[o] = inclusive entry-count prefixes at column 1024 / 2048 / 3072 / 4096.
__device__ int2 g_tab[OUT_DIM * CAP];
__device__ int4 g_bnd[OUT_DIM];

// ---------------------------------------------------------------------------
// Kernel 1: deterministic compaction of Phi rows.
// One block per output row o. Warp wp owns column quarter [wp*1024, wp*1024+1024);
// within a warp, thread's columns are {wp*1024 + k*32 + lane} (coalesced reads).
// Entry order = fixed (tid, k) order => identical every launch.
// ---------------------------------------------------------------------------
__global__ void __launch_bounds__(128) compact_kernel(const float* __restrict__ Phi) {
    const int o    = blockIdx.x;
    const int t    = threadIdx.x;      // 0..127
    const int wp   = t >> 5;           // quarter index 0..3
    const int lane = t & 31;
    const float* row = Phi + (size_t)o * IN_DIM;

    float rv[32];
    int cnt = 0;
#pragma unroll
    for (int k = 0; k < 32; k++) {
        rv[k] = row[wp * 1024 + k * 32 + lane];
        cnt += (rv[k] != 0.0f);
    }

    __shared__ int s[128];
    s[t] = cnt;
    __syncthreads();
    // Hillis-Steele inclusive scan (deterministic).
#pragma unroll
    for (int d = 1; d < 128; d <<= 1) {
        int v = (t >= d) ? s[t - d] : 0;
        __syncthreads();
        s[t] += v;
        __syncthreads();
    }
    const int off = s[t] - cnt;

    if (t == 0) {
        int b0 = s[31], b1 = s[63], b2 = s[95], b3 = s[127];
        g_bnd[o] = make_int4(min(b0, CAP), min(b1, CAP), min(b2, CAP), min(b3, CAP));
    }

    int idx = off;
#pragma unroll
    for (int k = 0; k < 32; k++) {
        float v = rv[k];
        if (v != 0.0f) {
            if (idx < CAP) {
                int c = wp * 1024 + k * 32 + lane;
                // store byte offset local to the KT-quarter
                g_tab[o * CAP + idx] = make_int2((c & (KT - 1)) * 4, __float_as_int(v));
            }
            idx++;
        }
    }
}

// ---------------------------------------------------------------------------
// Kernel 2: sparse out = x @ Phi^T.
// Block: 32 x-rows, all 1024 outputs, 4 K-phases of 1024 cols.
// lane == row  -> conflict-free smem reads (stride 1025).
// warp handles one output at a time -> table loads are warp-uniform broadcasts.
// Accumulators live in registers across phases; outputs staged in smem
// (aliasing the x tile) for coalesced global stores.
// ---------------------------------------------------------------------------
__global__ void __launch_bounds__(TPB, 1) spjl_kernel(
    const float* __restrict__ x, float* __restrict__ out, int nrows) {
    extern __shared__ float xs[];
    const int tid = threadIdx.x;
    const int w   = tid >> 5;        // warp 0..31 -> owns outputs [w*32, w*32+32)
    const int r   = tid & 31;        // lane == local row
    const size_t n0 = (size_t)blockIdx.x * R;
    const int ob = w * 32;

    float acc[32];
#pragma unroll
    for (int io = 0; io < 32; io++) acc[io] = 0.0f;

    const char* xrow = (const char*)(xs + r * XS_STRIDE);

    for (int p = 0; p < NPH; p++) {
        __syncthreads();   // previous phase readers done before overwriting tile
        // Load tile: 32 rows x 1024 cols. Coalesced LDG, conflict-free STS.
        for (int i = tid; i < R * KT; i += TPB) {
            int rr = i >> 10;
            int c  = i & (KT - 1);
            size_t gr = n0 + rr;
            float v = 0.0f;
            if (gr < (size_t)nrows) v = x[gr * IN_DIM + (size_t)p * KT + c];
            xs[rr * XS_STRIDE + c] = v;
        }
        __syncthreads();

#pragma unroll
        for (int io = 0; io < 32; io++) {
            const int o = ob + io;
            const int4 b = g_bnd[o];
            int jb = (p == 0) ? 0   : ((p == 1) ? b.x : ((p == 2) ? b.y : b.z));
            int je = (p == 0) ? b.x : ((p == 1) ? b.y : ((p == 2) ? b.z : b.w));
            const int2* tab = g_tab + o * CAP;
            float a = acc[io];
#pragma unroll 4
            for (int j = jb; j < je; j++) {
                int2 e = tab[j];   // warp-uniform address -> broadcast
                a = fmaf(__int_as_float(e.y), *(const float*)(xrow + e.x), a);
            }
            acc[io] = a;
        }
    }

    __syncthreads();
    // Stage results in smem (alias x tile). bank = (r + o) % 32 -> conflict-free.
#pragma unroll
    for (int io = 0; io < 32; io++) {
        xs[r * XS_STRIDE + ob + io] = acc[io];
    }
    __syncthreads();
    // Coalesced store.
    for (int i = tid; i < R * OUT_DIM; i += TPB) {
        int rr = i >> 10;
        int k  = i & (OUT_DIM - 1);
        size_t gr = n0 + rr;
        if (gr < (size_t)nrows)
            out[gr * OUT_DIM + k] = xs[rr * XS_STRIDE + k];
    }
}

extern "C" void kernel_launch(void* const* d_in, const int* in_sizes, int n_in,
                              void* d_out, int out_size) {
    const float* x   = (const float*)d_in[0];   // [N, 4096] fp32
    const float* Phi = (const float*)d_in[1];   // [1024, 4096] fp32
    float* out = (float*)d_out;                 // [N, 1024] fp32

    const int nrows = in_sizes[0] / IN_DIM;     // 16384
    const int grid  = (nrows + R - 1) / R;      // 512

    cudaFuncSetAttribute(spjl_kernel,
                         cudaFuncAttributeMaxDynamicSharedMemorySize, SMEM_BYTES);

    compact_kernel<<<OUT_DIM, 128>>>(Phi);
    spjl_kernel<<<grid, TPB, SMEM_BYTES>>>(x, out, nrows);
}

// round 3
// speedup vs baseline: 1.1362x; 1.1362x over previous
#include <cuda_runtime.h>
#include <stdint.h>

#define IN_DIM   4096
#define OUT_DIM  1024
#define CAP      96      // max entries kept per output row (mean ~40, ~9 sigma headroom)
#define RB       64      // x rows per block (2 per lane)
#define KT       512     // K columns per phase
#define NPH      8       // IN_DIM / KT
#define TPB      1024
#define OPW      16      // outputs per warp
#define OSPLIT   2       // output groups (512 outputs per block)
#define XS_STRIDE 513    // floats; 513 % 32 == 1 -> bank = (row + col) % 32, conflict-free
#define ROW32_BYTES (32 * XS_STRIDE * 4)   // 65664: smem byte offset from row L to row L+32
#define SMEM_BYTES  (RB * XS_STRIDE * 4)   // 131328

// Compacted sparse table for Phi (rebuilt every launch; deterministic).
// g_tab[o*CAP + j] = { byte offset of col within its KT-segment, fp32 value bits }
// g_seg[o*NPH + p] = { begin, end } entry indices for phase p of output o.
__device__ int2 g_tab[OUT_DIM * CAP];
__device__ int2 g_seg[OUT_DIM * NPH];

// ---------------------------------------------------------------------------
// Kernel 1: deterministic compaction of Phi rows into per-phase CSR segments.
// One block per output row o, 256 threads. Warp q owns column segment
// [q*512, (q+1)*512); lane u reads cols q*512 + k*32 + u (coalesced).
// Entries are grouped by segment; order within a segment is fixed (u, k).
// ---------------------------------------------------------------------------
__global__ void __launch_bounds__(256) compact_kernel(const float* __restrict__ Phi) {
    const int o = blockIdx.x;
    const int t = threadIdx.x;     // 0..255
    const int q = t >> 5;          // segment (phase) 0..7
    const int u = t & 31;
    const float* row = Phi + (size_t)o * IN_DIM;

    float rv[16];
    int cnt = 0;
#pragma unroll
    for (int k = 0; k < 16; k++) {
        rv[k] = row[q * KT + k * 32 + u];
        cnt += (rv[k] != 0.0f);
    }

    __shared__ int s[256];
    s[t] = cnt;
    __syncthreads();
#pragma unroll
    for (int d = 1; d < 256; d <<= 1) {
        int v = (t >= d) ? s[t - d] : 0;
        __syncthreads();
        s[t] += v;
        __syncthreads();
    }
    const int off = s[t] - cnt;   // exclusive prefix

    if (t < NPH) {
        int b0 = (t == 0) ? 0 : s[32 * t - 1];
        int b1 = s[32 * (t + 1) - 1];
        g_seg[o * NPH + t] = make_int2(min(b0, CAP), min(b1, CAP));
    }

    int idx = off;
#pragma unroll
    for (int k = 0; k < 16; k++) {
        float v = rv[k];
        if (v != 0.0f) {
            if (idx < CAP) {
                int c = q * KT + k * 32 + u;
                g_tab[o * CAP + idx] = make_int2((c & (KT - 1)) * 4, __float_as_int(v));
            }
            idx++;
        }
    }
}

// ---------------------------------------------------------------------------
// Kernel 2: sparse out = x @ Phi^T.
// Block: 64 x-rows (lane L handles rows L and L+32), 512 outputs
// (warp w owns 16), 8 K-phases of 512 cols. Each table entry feeds 2 FMAs.
// blockIdx: bit0 = output group (paired blocks share x rows -> L2 reuse).
// ---------------------------------------------------------------------------
__global__ void __launch_bounds__(TPB, 1) spjl_kernel(
    const float* __restrict__ x, float* __restrict__ out, int nrows) {
    extern __shared__ float xs[];
    const int tid = threadIdx.x;
    const int w   = tid >> 5;
    const int L   = tid & 31;
    const int rg  = blockIdx.x >> 1;
    const int og  = blockIdx.x & 1;
    const size_t n0 = (size_t)rg * RB;
    const int ob  = og * (OUT_DIM / OSPLIT) + w * OPW;   // global first output of warp

    float acc0[OPW], acc1[OPW];
#pragma unroll
    for (int io = 0; io < OPW; io++) { acc0[io] = 0.0f; acc1[io] = 0.0f; }

    const char* xrow = (const char*)(xs + L * XS_STRIDE);

    for (int p = 0; p < NPH; p++) {
        __syncthreads();   // previous phase readers done before overwrite
        // Load tile: 64 rows x 512 cols, float2 per thread-iteration.
#pragma unroll
        for (int it = 0; it < (RB * KT / 2) / TPB; it++) {
            int idx2 = tid + it * TPB;
            int rr   = idx2 >> 8;          // 256 float2 per row
            int c2   = idx2 & 255;
            size_t gr = n0 + rr;
            float2 v = make_float2(0.0f, 0.0f);
            if (gr < (size_t)nrows)
                v = *(const float2*)(x + gr * IN_DIM + (size_t)p * KT + c2 * 2);
            xs[rr * XS_STRIDE + c2 * 2]     = v.x;
            xs[rr * XS_STRIDE + c2 * 2 + 1] = v.y;
        }
        __syncthreads();

#pragma unroll
        for (int io = 0; io < OPW; io++) {
            const int o = ob + io;
            const int2 b = g_seg[o * NPH + p];
            const int2* tab = g_tab + o * CAP;
            float a0 = acc0[io], a1 = acc1[io];
#pragma unroll 4
            for (int j = b.x; j < b.y; j++) {
                int2 e = tab[j];                       // warp-uniform -> broadcast
                float phv = __int_as_float(e.y);
                float xv0 = *(const float*)(xrow + e.x);
                float xv1 = *(const float*)(xrow + ROW32_BYTES + e.x);
                a0 = fmaf(phv, xv0, a0);
                a1 = fmaf(phv, xv1, a1);
            }
            acc0[io] = a0; acc1[io] = a1;
        }
    }

    __syncthreads();
    // Stage results in smem (alias x tile); bank = (row + col) % 32, conflict-free.
#pragma unroll
    for (int io = 0; io < OPW; io++) {
        xs[L * XS_STRIDE        + w * OPW + io] = acc0[io];
        xs[(L + 32) * XS_STRIDE + w * OPW + io] = acc1[io];
    }
    __syncthreads();
    // Coalesced store of 64 rows x 512 outputs.
#pragma unroll
    for (int it = 0; it < (RB * (OUT_DIM / OSPLIT)) / TPB; it++) {
        int i  = tid + it * TPB;
        int rr = i >> 9;
        int k  = i & (OUT_DIM / OSPLIT - 1);
        size_t gr = n0 + rr;
        if (gr < (size_t)nrows)
            out[gr * OUT_DIM + og * (OUT_DIM / OSPLIT) + k] = xs[rr * XS_STRIDE + k];
    }
}

extern "C" void kernel_launch(void* const* d_in, const int* in_sizes, int n_in,
                              void* d_out, int out_size) {
    const float* x   = (const float*)d_in[0];   // [N, 4096] fp32
    const float* Phi = (const float*)d_in[1];   // [1024, 4096] fp32
    float* out = (float*)d_out;                 // [N, 1024] fp32

    const int nrows = in_sizes[0] / IN_DIM;              // 16384
    const int grid  = ((nrows + RB - 1) / RB) * OSPLIT;  // 512

    cudaFuncSetAttribute(spjl_kernel,
                         cudaFuncAttributeMaxDynamicSharedMemorySize, SMEM_BYTES);

    compact_kernel<<<OUT_DIM, 256>>>(Phi);
    spjl_kernel<<<grid, TPB, SMEM_BYTES>>>(x, out, nrows);
}

// round 4
// speedup vs baseline: 1.9805x; 1.7431x over previous
#include <cuda_runtime.h>
#include <stdint.h>

#define IN_DIM   4096
#define OUT_DIM  1024
#define RB       64      // x rows per block (2 per lane: L and L+32)
#define KT       512     // K columns per phase
#define NPH      8       // IN_DIM / KT
#define TPB      1024
#define OPW      16      // outputs per warp
#define OSPLIT   2       // output groups
#define OPB      (OUT_DIM / OSPLIT)   // 512 outputs per block
#define NSLICE   (NPH * OSPLIT)       // 16 (phase, outgroup) slices
#define SLICE_CAP 4096   // entries per slice in gmem (avg ~2560, +30 sigma safe)
#define XS_STRIDE 513    // 513 % 32 == 1 -> bank = (row + col) % 32, conflict-free
#define ROW32_BYTES (32 * XS_STRIDE * 4)
#define SMEM_BYTES  (RB * XS_STRIDE * 4 + SLICE_CAP * 8 + (OPB + 1) * 4)  // 166148

// Phase-major packed sparse table (rebuilt every launch; deterministic).
// Slice s = p*OSPLIT + og holds all entries of phase p for outputs [og*512, og*512+512),
// packed contiguously; g_soff[s][ol] = start of local output ol, g_soff[s][OPB] = total.
// Entry = { byte offset of col within its KT-segment, fp32 value bits }.
__device__ int  g_cnt[NPH * OUT_DIM];
__device__ int  g_soff[NSLICE][OPB + 1];
__device__ int2 g_ptab[NSLICE * SLICE_CAP];

// ---------------------------------------------------------------------------
// Prep 1: count nonzeros per (output o, phase q). Warp q of block o owns
// columns [q*512, (q+1)*512); coalesced reads.
// ---------------------------------------------------------------------------
__global__ void __launch_bounds__(256) count_kernel(const float* __restrict__ Phi) {
    const int o = blockIdx.x, t = threadIdx.x, q = t >> 5, u = t & 31;
    const float* row = Phi + (size_t)o * IN_DIM;
    int cnt = 0;
#pragma unroll
    for (int k = 0; k < 16; k++) cnt += (row[q * KT + k * 32 + u] != 0.0f);
#pragma unroll
    for (int d = 16; d; d >>= 1) cnt += __shfl_down_sync(0xffffffffu, cnt, d);
    if (u == 0) g_cnt[q * OUT_DIM + o] = cnt;
}

// ---------------------------------------------------------------------------
// Prep 2: exclusive scan of counts within each (phase, outgroup) slice.
// ---------------------------------------------------------------------------
__global__ void __launch_bounds__(OPB) scan_kernel() {
    const int s = blockIdx.x;          // s = p*OSPLIT + og
    const int p = s >> 1, og = s & 1, t = threadIdx.x;
    __shared__ int sh[OPB];
    int c = g_cnt[p * OUT_DIM + og * OPB + t];
    sh[t] = c;
    __syncthreads();
#pragma unroll
    for (int d = 1; d < OPB; d <<= 1) {
        int v = (t >= d) ? sh[t - d] : 0;
        __syncthreads();
        sh[t] += v;
        __syncthreads();
    }
    g_soff[s][t] = min(sh[t] - c, SLICE_CAP);
    if (t == OPB - 1) g_soff[s][OPB] = min(sh[t], SLICE_CAP);
}

// ---------------------------------------------------------------------------
// Prep 3: fill packed table. Deterministic order: within (o, phase), entries
// ordered by (lane, k) via intra-warp exclusive scan.
// ---------------------------------------------------------------------------
__global__ void __launch_bounds__(256) fill_kernel(const float* __restrict__ Phi) {
    const int o = blockIdx.x, t = threadIdx.x, q = t >> 5, u = t & 31;
    const int og = (o >= OPB) ? 1 : 0;
    const int ol = o - og * OPB;
    const int s  = q * OSPLIT + og;
    const float* row = Phi + (size_t)o * IN_DIM;

    float rv[16];
    int cnt = 0;
#pragma unroll
    for (int k = 0; k < 16; k++) { rv[k] = row[q * KT + k * 32 + u]; cnt += (rv[k] != 0.0f); }

    int ex = cnt;
#pragma unroll
    for (int d = 1; d < 32; d <<= 1) {
        int v = __shfl_up_sync(0xffffffffu, ex, d);
        if (u >= d) ex += v;
    }
    ex -= cnt;   // exclusive prefix over lanes

    int dst = g_soff[s][ol] + ex;
#pragma unroll
    for (int k = 0; k < 16; k++) {
        float v = rv[k];
        if (v != 0.0f) {
            if (dst < SLICE_CAP)
                g_ptab[s * SLICE_CAP + dst] = make_int2((k * 32 + u) * 4, __float_as_int(v));
            dst++;
        }
    }
}

// ---------------------------------------------------------------------------
// Main: sparse out = x @ Phi^T. Block: 64 x-rows (lane L -> rows L, L+32),
// 512 outputs (warp w -> 16), 8 K-phases. Per phase the block stages both the
// x tile AND its table slice in smem; the hot loop touches smem only.
// ---------------------------------------------------------------------------
__global__ void __launch_bounds__(TPB, 1) spjl_kernel(
    const float* __restrict__ x, float* __restrict__ out, int nrows) {
    extern __shared__ float xs[];                       // x tile [RB * XS_STRIDE]
    int2* st_tab = (int2*)(xs + RB * XS_STRIDE);        // staged slice entries
    int*  st_off = (int*)(st_tab + SLICE_CAP);          // staged offsets [OPB+1]

    const int tid = threadIdx.x;
    const int w   = tid >> 5;
    const int L   = tid & 31;
    const int rg  = blockIdx.x >> 1;
    const int og  = blockIdx.x & 1;
    const size_t n0 = (size_t)rg * RB;
    const int olb = w * OPW;                            // warp's first local output

    float acc0[OPW], acc1[OPW];
#pragma unroll
    for (int io = 0; io < OPW; io++) { acc0[io] = 0.0f; acc1[io] = 0.0f; }

    const char* xrow = (const char*)(xs + L * XS_STRIDE);

    for (int p = 0; p < NPH; p++) {
        const int s = p * OSPLIT + og;
        const int len = g_soff[s][OPB];
        __syncthreads();   // previous phase readers done before overwrite

        // Stage x tile: 64 rows x 512 cols (coalesced LDG.64, conflict-free STS).
#pragma unroll
        for (int it = 0; it < (RB * KT / 2) / TPB; it++) {
            int idx2 = tid + it * TPB;
            int rr   = idx2 >> 8;
            int c2   = idx2 & 255;
            size_t gr = n0 + rr;
            float2 v = make_float2(0.0f, 0.0f);
            if (gr < (size_t)nrows)
                v = *(const float2*)(x + gr * IN_DIM + (size_t)p * KT + c2 * 2);
            xs[rr * XS_STRIDE + c2 * 2]     = v.x;
            xs[rr * XS_STRIDE + c2 * 2 + 1] = v.y;
        }
        // Stage table slice + offsets (coalesced).
        if (tid <= OPB) st_off[tid] = g_soff[s][tid];
        for (int i = tid; i < len; i += TPB) st_tab[i] = g_ptab[s * SLICE_CAP + i];
        __syncthreads();

#pragma unroll
        for (int io = 0; io < OPW; io++) {
            const int ol = olb + io;
            int jb = st_off[ol];
            int je = st_off[ol + 1];
            float a0 = acc0[io], a1 = acc1[io];
#pragma unroll 4
            for (int j = jb; j < je; j++) {
                int2 e = st_tab[j];                    // warp-uniform smem broadcast
                float phv = __int_as_float(e.y);
                float xv0 = *(const float*)(xrow + e.x);
                float xv1 = *(const float*)(xrow + ROW32_BYTES + e.x);
                a0 = fmaf(phv, xv0, a0);
                a1 = fmaf(phv, xv1, a1);
            }
            acc0[io] = a0; acc1[io] = a1;
        }
    }

    __syncthreads();
    // Stage results (alias x tile); bank = (row + col) % 32 -> conflict-free.
#pragma unroll
    for (int io = 0; io < OPW; io++) {
        xs[L * XS_STRIDE        + olb + io] = acc0[io];
        xs[(L + 32) * XS_STRIDE + olb + io] = acc1[io];
    }
    __syncthreads();
    // Coalesced store of 64 rows x 512 outputs.
#pragma unroll
    for (int it = 0; it < (RB * OPB) / TPB; it++) {
        int i  = tid + it * TPB;
        int rr = i >> 9;
        int k  = i & (OPB - 1);
        size_t gr = n0 + rr;
        if (gr < (size_t)nrows)
            out[gr * OUT_DIM + og * OPB + k] = xs[rr * XS_STRIDE + k];
    }
}

extern "C" void kernel_launch(void* const* d_in, const int* in_sizes, int n_in,
                              void* d_out, int out_size) {
    const float* x   = (const float*)d_in[0];   // [N, 4096] fp32
    const float* Phi = (const float*)d_in[1];   // [1024, 4096] fp32
    float* out = (float*)d_out;                 // [N, 1024] fp32

    const int nrows = in_sizes[0] / IN_DIM;              // 16384
    const int grid  = ((nrows + RB - 1) / RB) * OSPLIT;  // 512

    cudaFuncSetAttribute(spjl_kernel,
                         cudaFuncAttributeMaxDynamicSharedMemorySize, SMEM_BYTES);

    count_kernel<<<OUT_DIM, 256>>>(Phi);
    scan_kernel<<<NSLICE, OPB>>>();
    fill_kernel<<<OUT_DIM, 256>>>(Phi);
    spjl_kernel<<<grid, TPB, SMEM_BYTES>>>(x, out, nrows);
}